// round 16
// baseline (speedup 1.0000x reference)
#include <cuda_runtime.h>
#include <cstdint>
#include <cstddef>

#define TT 16            // tokens per tile
#define NC 1024          // flattened stream dim (n*C)
#define FULLMASK 0xFFFFFFFFu

// padded partial-dots layout: [kh][token][row*8 + coset], token stride 208
#define PD_TOK 208
#define PD_KH  (TT*PD_TOK)   // 3328

typedef unsigned long long ull;

// ---- packed f32x2 helpers (Blackwell FFMA2 path) ----
__device__ __forceinline__ void fma2(ull &acc, ull a, ull b) {
    asm("fma.rn.f32x2 %0, %1, %2, %0;" : "+l"(acc) : "l"(a), "l"(b));
}
__device__ __forceinline__ ull pack2(float x, float y) {
    ull r;
    asm("mov.b64 %0, {%1, %2};" : "=l"(r)
        : "r"(__float_as_uint(x)), "r"(__float_as_uint(y)));
    return r;
}
__device__ __forceinline__ float hadd2(ull v) {
    unsigned lo, hi;
    asm("mov.b64 {%0, %1}, %2;" : "=r"(lo), "=r"(hi) : "l"(v));
    return __uint_as_float(lo) + __uint_as_float(hi);
}

__device__ __forceinline__ void cp_async16(uint32_t saddr, const void* gaddr) {
    asm volatile("cp.async.cg.shared.global [%0], [%1], 16;"
                 :: "r"(saddr), "l"(gaddr));
}

// sum of 8 consecutive floats in smem
__device__ __forceinline__ float sum8(const float* p) {
    float4 a = *reinterpret_cast<const float4*>(p);
    float4 b = *reinterpret_cast<const float4*>(p + 4);
    return ((a.x + a.y) + (a.z + a.w)) + ((b.x + b.y) + (b.z + b.w));
}

// smem layout (floats):
//   xbuf0[TT*NC] | xbuf1[TT*NC] | rstd[TT] | pdots[2*PD_KH] | coef[TT*16]
#define SMEM_FLOATS (2*TT*NC + TT + 2*PD_KH + TT*16)

__global__ __launch_bounds__(256, 1)
void fused_streams_kernel(const float* __restrict__ x,
                          const float* __restrict__ scale,
                          const float* __restrict__ w_pre,
                          const float* __restrict__ w_post,
                          const float* __restrict__ w_res,
                          const float* __restrict__ p_apre,
                          const float* __restrict__ p_apost,
                          const float* __restrict__ p_ares,
                          const float* __restrict__ b_pre,
                          const float* __restrict__ b_post,
                          const float* __restrict__ b_res,
                          float* __restrict__ out,
                          int nTiles)
{
    extern __shared__ float smem[];
    float* xbuf0 = smem;
    float* xbuf1 = smem + TT*NC;
    float* rstd  = smem + 2*TT*NC;       // [TT]
    float* pdots = rstd + TT;            // [2][TT][PD_TOK]
    float* coef  = pdots + 2*PD_KH;      // [TT][16]

    const int tid  = threadIdx.x;
    const int lane = tid & 31;
    const int warp = tid >> 5;           // 0..7
    const int g    = warp >> 1;          // row group 0..3 (6 rows each)
    const int kh   = warp & 1;           // K-half 0/1

    const float a_pre  = *p_apre;
    const float a_post = *p_apost;
    const float a_res  = *p_ares;

    // ---- Phase C per-thread constants (cell fixed for the lifetime) ----
    const int c_cell = tid & 15;                       // 4x4 cell id
    const float c_bres = b_res[c_cell];
    const float c_bph  = (c_cell < 4) ? b_pre[c_cell]
                       : (c_cell < 8) ? b_post[c_cell - 4] : 0.f;

    // ---- weight slice into registers (scale folded), 2-way K split ----
    // warp (g,kh): rows 6g..6g+5, K-half kh (512 floats). Lane l owns float4
    // chunks idx = kh*128 + l + 32m, m=0..3 -> 8 ull per row, 6 rows = 48 ull.
    ull wr[6][8];
#pragma unroll
    for (int q = 0; q < 6; q++) {
        int r = g*6 + q;
        const float* wrow = (r < 4)  ? (w_pre  + r*NC)
                          : (r < 8)  ? (w_post + (r-4)*NC)
                                     : (w_res  + (r-8)*NC);
        const float4* wrow4 = reinterpret_cast<const float4*>(wrow);
        const float4* sc4   = reinterpret_cast<const float4*>(scale);
#pragma unroll
        for (int m = 0; m < 4; m++) {
            int idx = kh*128 + lane + 32*m;
            float4 wv = wrow4[idx];
            float4 sv = sc4[idx];
            wr[q][2*m]   = pack2(wv.x * sv.x, wv.y * sv.y);
            wr[q][2*m+1] = pack2(wv.z * sv.z, wv.w * sv.w);
        }
    }

    uint32_t sb0 = (uint32_t)__cvta_generic_to_shared(xbuf0);
    uint32_t sb1 = (uint32_t)__cvta_generic_to_shared(xbuf1);

    int tile = blockIdx.x;

    // prefetch first tile into buffer 0
    if (tile < nTiles) {
        const char* src = (const char*)(x + (size_t)tile * (TT*NC));
#pragma unroll
        for (int j = 0; j < 16; j++) {
            int off = j*4096 + tid*16;
            cp_async16(sb0 + off, src + off);
        }
    }
    asm volatile("cp.async.commit_group;");

    int buf = 0;
    for (; tile < nTiles; tile += gridDim.x) {
        // prefetch next tile into the other buffer
        int nxt = tile + gridDim.x;
        if (nxt < nTiles) {
            uint32_t sbn = buf ? sb0 : sb1;
            const char* src = (const char*)(x + (size_t)nxt * (TT*NC));
#pragma unroll
            for (int j = 0; j < 16; j++) {
                int off = j*4096 + tid*16;
                cp_async16(sbn + off, src + off);
            }
        }
        asm volatile("cp.async.commit_group;");
        asm volatile("cp.async.wait_group 1;");   // current tile resident
        __syncthreads();

        const float* xb = buf ? xbuf1 : xbuf0;

        // ---- Phase A: per-token RMS rstd (16 threads per token) ----
        {
            int t   = (warp << 1) + (lane >> 4);
            int sub = lane & 15;
            const float4* x4 = reinterpret_cast<const float4*>(xb) + t*256;
            float s = 0.f;
#pragma unroll
            for (int i = 0; i < 16; i++) {
                float4 v = x4[sub + 16*i];
                s += v.x*v.x + v.y*v.y + v.z*v.z + v.w*v.w;
            }
            s += __shfl_xor_sync(FULLMASK, s, 1);
            s += __shfl_xor_sync(FULLMASK, s, 2);
            s += __shfl_xor_sync(FULLMASK, s, 4);
            s += __shfl_xor_sync(FULLMASK, s, 8);
            if (sub == 0) rstd[t] = rsqrtf(s * (1.0f/1024.0f) + 1e-5f);
        }

        // ---- Phase B: partial dots, warp = 6 rows x K/2, 2-token batches ----
        // Reduction truncated at the 8-lane-coset level; octets store 3
        // partial values each (3 conflict-free STS.32), final sums in Phase C.
        for (int t = 0; t < TT; t += 2) {
            const float4* xA = reinterpret_cast<const float4*>(xb + t*NC)     + kh*128;
            const float4* xB = reinterpret_cast<const float4*>(xb + (t+1)*NC) + kh*128;
            ull accA[6], accB[6];
#pragma unroll
            for (int q = 0; q < 6; q++) { accA[q] = 0ull; accB[q] = 0ull; }
#pragma unroll
            for (int m = 0; m < 4; m++) {
                float4 va = xA[lane + 32*m];
                float4 vb = xB[lane + 32*m];
                ull alo = pack2(va.x, va.y), ahi = pack2(va.z, va.w);
                ull blo = pack2(vb.x, vb.y), bhi = pack2(vb.z, vb.w);
#pragma unroll
                for (int q = 0; q < 6; q++) {
                    fma2(accA[q], wr[q][2*m],   alo);
                    fma2(accA[q], wr[q][2*m+1], ahi);
                    fma2(accB[q], wr[q][2*m],   blo);
                    fma2(accB[q], wr[q][2*m+1], bhi);
                }
            }
            float dA[6], dB[6];
#pragma unroll
            for (int q = 0; q < 6; q++) { dA[q] = hadd2(accA[q]); dB[q] = hadd2(accB[q]); }
            // coset reduce: after xor16+xor8, every lane holds the sum over
            // its 4-lane coset {l, l^8, l^16, l^24} for all 12 values.
#pragma unroll
            for (int q = 0; q < 6; q++) {
                dA[q] += __shfl_xor_sync(FULLMASK, dA[q], 16);
                dB[q] += __shfl_xor_sync(FULLMASK, dB[q], 16);
            }
#pragma unroll
            for (int q = 0; q < 6; q++) {
                dA[q] += __shfl_xor_sync(FULLMASK, dA[q], 8);
                dB[q] += __shfl_xor_sync(FULLMASK, dB[q], 8);
            }
            // octet o stores 3 values' coset-(lane&7) partials:
            //   o=0: (t,   rows g*6+0..2)   o=1: (t,   rows g*6+3..5)
            //   o=2: (t+1, rows g*6+0..2)   o=3: (t+1, rows g*6+3..5)
            {
                int o = lane >> 3, c = lane & 7;
                int tok = t + (o >> 1);
                int qb  = (o & 1) * 3;
                float s0 = (o == 0) ? dA[0] : (o == 1) ? dA[3] : (o == 2) ? dB[0] : dB[3];
                float s1 = (o == 0) ? dA[1] : (o == 1) ? dA[4] : (o == 2) ? dB[1] : dB[4];
                float s2 = (o == 0) ? dA[2] : (o == 1) ? dA[5] : (o == 2) ? dB[2] : dB[5];
                float* dp = pdots + kh*PD_KH + tok*PD_TOK + (g*6 + qb)*8 + c;
                dp[0]  = s0;
                dp[8]  = s1;
                dp[16] = s2;
            }
        }
        __syncthreads();

        // ---- Phase C: sinkhorn + routing coefficients (cell-parallel) ----
        {
            int t    = tid >> 4;        // token 0..15
            int cell = c_cell;          // i = cell>>2, j = cell&3
            int grp  = lane & 16;       // 16-lane group base within warp
            float rs = rstd[t];

            // res-logit row (8+cell): sum 8 cosets per K-half
            const float* pr = pdots + t*PD_TOK + (8 + cell)*8;
            float rsum = sum8(pr) + sum8(pr + PD_KH);
            // gate row (cell, valid for cell<8)
            const float* pg = pdots + t*PD_TOK + cell*8;
            float gsum = sum8(pg) + sum8(pg + PD_KH);

            float z = a_res * (rsum * rs) + c_bres;
            // 2-level max with independent fetches
            float z1 = __shfl_xor_sync(FULLMASK, z, 1);
            float z2 = __shfl_xor_sync(FULLMASK, z, 2);
            float z3 = __shfl_xor_sync(FULLMASK, z, 3);
            float m1 = fmaxf(fmaxf(z, z1), fmaxf(z2, z3));
            float m4 = __shfl_xor_sync(FULLMASK, m1, 4);
            float m8 = __shfl_xor_sync(FULLMASK, m1, 8);
            float mc = __shfl_xor_sync(FULLMASK, m1, 12);
            float mx = fmaxf(fmaxf(m1, m4), fmaxf(m8, mc));
            float p = __expf(z - mx);

#pragma unroll
            for (int it = 0; it < 20; it++) {
                // column sum (over i): lanes differing in bits 2,3
                float c1 = __shfl_xor_sync(FULLMASK, p, 4);
                float c2 = __shfl_xor_sync(FULLMASK, p, 8);
                float c3 = __shfl_xor_sync(FULLMASK, p, 12);
                p = __fdividef(p, ((p + c1) + (c2 + c3)) + 1e-8f);
                // row sum (over j): lanes differing in bits 0,1
                float r1 = __shfl_xor_sync(FULLMASK, p, 1);
                float r2 = __shfl_xor_sync(FULLMASK, p, 2);
                float r3 = __shfl_xor_sync(FULLMASK, p, 3);
                p = __fdividef(p, ((p + r1) + (r2 + r3)) + 1e-8f);
            }

            float hv = 0.f;
            float dd = gsum * rs;   // valid for cell < 8
            if (cell < 4) {
                hv = __fdividef(1.0f, 1.0f + __expf(-(a_pre * dd + c_bph)));
            } else if (cell < 8) {
                hv = __fdividef(2.0f, 1.0f + __expf(-(a_post * dd + c_bph)));
            }
            int ii = cell >> 2, jj = cell & 3;
            float hpre_j  = __shfl_sync(FULLMASK, hv, grp + jj);
            float hpost_i = __shfl_sync(FULLMASK, hv, grp + 4 + ii);
            coef[t*16 + cell] = p + hpost_i * hpre_j;
        }
        __syncthreads();

        // ---- Phase D: mixing, x read from gmem (L2-hot from cp.async.cg) ----
        {
            int c4 = tid & 63;     // float4 column chunk (C=256 -> 64 chunks)
            int tg = tid >> 6;     // token group 0..3
            const float4* cf4 = reinterpret_cast<const float4*>(coef);
            const float4* xg  = reinterpret_cast<const float4*>(x)
                              + (size_t)tile * (TT*NC/4);
#pragma unroll
            for (int ttk = 0; ttk < 4; ttk++) {
                int t = tg*4 + ttk;
                float4 m0 = cf4[t*4 + 0];
                float4 m1 = cf4[t*4 + 1];
                float4 m2 = cf4[t*4 + 2];
                float4 m3 = cf4[t*4 + 3];
                const float4* x4 = xg + t*256;
                float4 xj0 = __ldg(x4 + 0*64 + c4);
                float4 xj1 = __ldg(x4 + 1*64 + c4);
                float4 xj2 = __ldg(x4 + 2*64 + c4);
                float4 xj3 = __ldg(x4 + 3*64 + c4);
                float4* o4 = reinterpret_cast<float4*>(out)
                           + ((size_t)tile*TT + t) * 256;
                float4 o;
                o.x = m0.x*xj0.x + m0.y*xj1.x + m0.z*xj2.x + m0.w*xj3.x;
                o.y = m0.x*xj0.y + m0.y*xj1.y + m0.z*xj2.y + m0.w*xj3.y;
                o.z = m0.x*xj0.z + m0.y*xj1.z + m0.z*xj2.z + m0.w*xj3.z;
                o.w = m0.x*xj0.w + m0.y*xj1.w + m0.z*xj2.w + m0.w*xj3.w;
                o4[0*64 + c4] = o;
                o.x = m1.x*xj0.x + m1.y*xj1.x + m1.z*xj2.x + m1.w*xj3.x;
                o.y = m1.x*xj0.y + m1.y*xj1.y + m1.z*xj2.y + m1.w*xj3.y;
                o.z = m1.x*xj0.z + m1.y*xj1.z + m1.z*xj2.z + m1.w*xj3.z;
                o.w = m1.x*xj0.w + m1.y*xj1.w + m1.z*xj2.w + m1.w*xj3.w;
                o4[1*64 + c4] = o;
                o.x = m2.x*xj0.x + m2.y*xj1.x + m2.z*xj2.x + m2.w*xj3.x;
                o.y = m2.x*xj0.y + m2.y*xj1.y + m2.z*xj2.y + m2.w*xj3.y;
                o.z = m2.x*xj0.z + m2.y*xj1.z + m2.z*xj2.z + m2.w*xj3.z;
                o.w = m2.x*xj0.w + m2.y*xj1.w + m2.z*xj2.w + m2.w*xj3.w;
                o4[2*64 + c4] = o;
                o.x = m3.x*xj0.x + m3.y*xj1.x + m3.z*xj2.x + m3.w*xj3.x;
                o.y = m3.x*xj0.y + m3.y*xj1.y + m3.z*xj2.y + m3.w*xj3.y;
                o.z = m3.x*xj0.z + m3.y*xj1.z + m3.z*xj2.z + m3.w*xj3.z;
                o.w = m3.x*xj0.w + m3.y*xj1.w + m3.z*xj2.w + m3.w*xj3.w;
                o4[3*64 + c4] = o;
            }
        }
        // no trailing barrier: Phase D no longer reads xbuf; the B->C barrier
        // already orders xbuf reads against the next iteration's prefetch.
        buf ^= 1;
    }
}

extern "C" void kernel_launch(void* const* d_in, const int* in_sizes, int n_in,
                              void* d_out, int out_size) {
    const float* x      = (const float*)d_in[0];
    const float* scale  = (const float*)d_in[1];
    const float* w_pre  = (const float*)d_in[2];
    const float* w_post = (const float*)d_in[3];
    const float* w_res  = (const float*)d_in[4];
    const float* apre   = (const float*)d_in[5];
    const float* apost  = (const float*)d_in[6];
    const float* ares   = (const float*)d_in[7];
    const float* b_pre  = (const float*)d_in[8];
    const float* b_post = (const float*)d_in[9];
    const float* b_res  = (const float*)d_in[10];
    float* out = (float*)d_out;

    int BT = in_sizes[0] / NC;        // 32768 tokens
    int nTiles = BT / TT;             // 2048

    size_t smemBytes = (size_t)SMEM_FLOATS * sizeof(float);   // ~155 KB

    int dev = 0;
    cudaGetDevice(&dev);
    int sms = 148;
    cudaDeviceGetAttribute(&sms, cudaDevAttrMultiProcessorCount, dev);
    cudaFuncSetAttribute(fused_streams_kernel,
                         cudaFuncAttributeMaxDynamicSharedMemorySize,
                         (int)smemBytes);

    int grid = sms < nTiles ? sms : nTiles;

    fused_streams_kernel<<<grid, 256, smemBytes>>>(
        x, scale, w_pre, w_post, w_res,
        apre, apost, ares, b_pre, b_post, b_res,
        out, nTiles);
}

// round 17
// speedup vs baseline: 1.0736x; 1.0736x over previous
#include <cuda_runtime.h>
#include <cstdint>
#include <cstddef>

#define TT 16            // tokens per tile
#define NC 1024          // flattened stream dim (n*C)
#define FULLMASK 0xFFFFFFFFu

typedef unsigned long long ull;

// ---- packed f32x2 helpers (Blackwell FFMA2 path) ----
__device__ __forceinline__ void fma2(ull &acc, ull a, ull b) {
    asm("fma.rn.f32x2 %0, %1, %2, %0;" : "+l"(acc) : "l"(a), "l"(b));
}
__device__ __forceinline__ ull pack2(float x, float y) {
    ull r;
    asm("mov.b64 %0, {%1, %2};" : "=l"(r)
        : "r"(__float_as_uint(x)), "r"(__float_as_uint(y)));
    return r;
}
__device__ __forceinline__ float hadd2(ull v) {
    unsigned lo, hi;
    asm("mov.b64 {%0, %1}, %2;" : "=r"(lo), "=r"(hi) : "l"(v));
    return __uint_as_float(lo) + __uint_as_float(hi);
}

__device__ __forceinline__ void cp_async16(uint32_t saddr, const void* gaddr) {
    asm volatile("cp.async.cg.shared.global [%0], [%1], 16;"
                 :: "r"(saddr), "l"(gaddr));
}

// smem layout (floats):
//   xbuf0[TT*NC] | xbuf1[TT*NC] | rstd[TT] | dotsp[2][TT][24] | coef[TT*16]
#define SMEM_FLOATS (2*TT*NC + TT + 2*TT*24 + TT*16)

__global__ __launch_bounds__(256, 1)
void fused_streams_kernel(const float* __restrict__ x,
                          const float* __restrict__ scale,
                          const float* __restrict__ w_pre,
                          const float* __restrict__ w_post,
                          const float* __restrict__ w_res,
                          const float* __restrict__ p_apre,
                          const float* __restrict__ p_apost,
                          const float* __restrict__ p_ares,
                          const float* __restrict__ b_pre,
                          const float* __restrict__ b_post,
                          const float* __restrict__ b_res,
                          float* __restrict__ out,
                          int nTiles)
{
    extern __shared__ float smem[];
    float* xbuf0 = smem;
    float* xbuf1 = smem + TT*NC;
    float* rstd  = smem + 2*TT*NC;
    float* dotsp = rstd + TT;           // [2][TT][24]
    float* coef  = dotsp + 2*TT*24;     // [TT][16]

    const int tid  = threadIdx.x;
    const int lane = tid & 31;
    const int warp = tid >> 5;
    const int g    = warp >> 1;         // row group 0..3 (6 rows each)
    const int kh   = warp & 1;          // K-half 0/1

    const float a_pre  = *p_apre;
    const float a_post = *p_apost;
    const float a_res  = *p_ares;

    // ---- Phase C per-thread constants (cell fixed for the lifetime) ----
    const int c_cell = tid & 15;                       // 4x4 cell id
    const float c_bres = b_res[c_cell];
    const float c_bph  = (c_cell < 4) ? b_pre[c_cell]
                       : (c_cell < 8) ? b_post[c_cell - 4] : 0.f;

    // ---- weight slice into registers (scale folded), 2-way K split ----
    // warp (g,kh): rows 6g..6g+5, K-half kh (512 floats). Lane l owns float4
    // chunks idx = kh*128 + l + 32m, m=0..3 -> 8 ull per row, 6 rows = 48 ull.
    ull wr[6][8];
#pragma unroll
    for (int q = 0; q < 6; q++) {
        int r = g*6 + q;
        const float* wrow = (r < 4)  ? (w_pre  + r*NC)
                          : (r < 8)  ? (w_post + (r-4)*NC)
                                     : (w_res  + (r-8)*NC);
        const float4* wrow4 = reinterpret_cast<const float4*>(wrow);
        const float4* sc4   = reinterpret_cast<const float4*>(scale);
#pragma unroll
        for (int m = 0; m < 4; m++) {
            int idx = kh*128 + lane + 32*m;
            float4 wv = wrow4[idx];
            float4 sv = sc4[idx];
            wr[q][2*m]   = pack2(wv.x * sv.x, wv.y * sv.y);
            wr[q][2*m+1] = pack2(wv.z * sv.z, wv.w * sv.w);
        }
    }

    uint32_t sb0 = (uint32_t)__cvta_generic_to_shared(xbuf0);
    uint32_t sb1 = (uint32_t)__cvta_generic_to_shared(xbuf1);

    int tile = blockIdx.x;

    // prefetch first tile into buffer 0
    if (tile < nTiles) {
        const char* src = (const char*)(x + (size_t)tile * (TT*NC));
#pragma unroll
        for (int j = 0; j < 16; j++) {
            int off = j*4096 + tid*16;
            cp_async16(sb0 + off, src + off);
        }
    }
    asm volatile("cp.async.commit_group;");

    int buf = 0;
    for (; tile < nTiles; tile += gridDim.x) {
        // prefetch next tile into the other buffer
        int nxt = tile + gridDim.x;
        if (nxt < nTiles) {
            uint32_t sbn = buf ? sb0 : sb1;
            const char* src = (const char*)(x + (size_t)nxt * (TT*NC));
#pragma unroll
            for (int j = 0; j < 16; j++) {
                int off = j*4096 + tid*16;
                cp_async16(sbn + off, src + off);
            }
        }
        asm volatile("cp.async.commit_group;");
        asm volatile("cp.async.wait_group 1;");   // current tile's group done
        __syncthreads();

        const float* xb = buf ? xbuf1 : xbuf0;

        // ---- Phase A: per-token RMS rstd (16 threads per token) ----
        {
            int t   = (warp << 1) + (lane >> 4);
            int sub = lane & 15;
            const float4* x4 = reinterpret_cast<const float4*>(xb) + t*256;
            float s = 0.f;
#pragma unroll
            for (int i = 0; i < 16; i++) {
                float4 v = x4[sub + 16*i];
                s += v.x*v.x + v.y*v.y + v.z*v.z + v.w*v.w;
            }
            s += __shfl_xor_sync(FULLMASK, s, 1);
            s += __shfl_xor_sync(FULLMASK, s, 2);
            s += __shfl_xor_sync(FULLMASK, s, 4);
            s += __shfl_xor_sync(FULLMASK, s, 8);
            if (sub == 0) rstd[t] = rsqrtf(s * (1.0f/1024.0f) + 1e-5f);
        }

        // ---- Phase B: partial dots, warp = 6 rows x K/2, 2-token batches ----
        // Batch order is STAGGERED per warp (warp w starts at pair w) so the
        // 8 warps sit at different loop phases and their LDS/shuffle-tree
        // stalls decorrelate instead of aligning block-wide.
        for (int i = 0; i < 8; i++) {
            const int t = ((i + warp) & 7) * 2;
            const float4* xA = reinterpret_cast<const float4*>(xb + t*NC)     + kh*128;
            const float4* xB = reinterpret_cast<const float4*>(xb + (t+1)*NC) + kh*128;
            ull accA[6], accB[6];
#pragma unroll
            for (int q = 0; q < 6; q++) { accA[q] = 0ull; accB[q] = 0ull; }
#pragma unroll
            for (int m = 0; m < 4; m++) {
                float4 va = xA[lane + 32*m];
                float4 vb = xB[lane + 32*m];
                ull alo = pack2(va.x, va.y), ahi = pack2(va.z, va.w);
                ull blo = pack2(vb.x, vb.y), bhi = pack2(vb.z, vb.w);
#pragma unroll
                for (int q = 0; q < 6; q++) {
                    fma2(accA[q], wr[q][2*m],   alo);
                    fma2(accA[q], wr[q][2*m+1], ahi);
                    fma2(accB[q], wr[q][2*m],   blo);
                    fma2(accB[q], wr[q][2*m+1], bhi);
                }
            }
            float dA[6], dB[6];
#pragma unroll
            for (int q = 0; q < 6; q++) { dA[q] = hadd2(accA[q]); dB[q] = hadd2(accB[q]); }
            // coset reduce: after xor16+xor8, lane l holds (l mod 8)-coset sums
#pragma unroll
            for (int q = 0; q < 6; q++) {
                dA[q] += __shfl_xor_sync(FULLMASK, dA[q], 16);
                dB[q] += __shfl_xor_sync(FULLMASK, dB[q], 16);
            }
#pragma unroll
            for (int q = 0; q < 6; q++) {
                dA[q] += __shfl_xor_sync(FULLMASK, dA[q], 8);
                dB[q] += __shfl_xor_sync(FULLMASK, dB[q], 8);
            }
            // lanes 0-7 -> value 0, 8-15 -> value 1, 16-23 -> value 2
            float e1A = (lane < 8) ? dA[0] : (lane < 16) ? dA[1] : dA[2];
            float e2A = (lane < 8) ? dA[3] : (lane < 16) ? dA[4] : dA[5];
            float e1B = (lane < 8) ? dB[0] : (lane < 16) ? dB[1] : dB[2];
            float e2B = (lane < 8) ? dB[3] : (lane < 16) ? dB[4] : dB[5];
#pragma unroll
            for (int m = 4; m >= 1; m >>= 1) {
                e1A += __shfl_xor_sync(FULLMASK, e1A, m);
                e2A += __shfl_xor_sync(FULLMASK, e2A, m);
                e1B += __shfl_xor_sync(FULLMASK, e1B, m);
                e2B += __shfl_xor_sync(FULLMASK, e2B, m);
            }
            if ((lane & 7) == 0 && lane < 24) {
                int r = lane >> 3;                    // 0,1,2
                float* dp = dotsp + kh*(TT*24);
                dp[t*24     + g*6 + r]     = e1A;
                dp[t*24     + g*6 + 3 + r] = e2A;
                dp[(t+1)*24 + g*6 + r]     = e1B;
                dp[(t+1)*24 + g*6 + 3 + r] = e2B;
            }
        }
        __syncthreads();

        // ---- Phase C: sinkhorn + routing coefficients (thread per cell) ----
        {
            int t    = tid >> 4;        // token 0..15
            int cell = c_cell;          // i = cell>>2, j = cell&3
            int grp  = lane & 16;       // 16-lane group base within warp
            float rs = rstd[t];
            const float* dp0 = dotsp + t*24;
            const float* dp1 = dotsp + TT*24 + t*24;

            float z = a_res * ((dp0[8 + cell] + dp1[8 + cell]) * rs) + c_bres;
            // 2-level max with independent fetches
            float z1 = __shfl_xor_sync(FULLMASK, z, 1);
            float z2 = __shfl_xor_sync(FULLMASK, z, 2);
            float z3 = __shfl_xor_sync(FULLMASK, z, 3);
            float m1 = fmaxf(fmaxf(z, z1), fmaxf(z2, z3));
            float m4 = __shfl_xor_sync(FULLMASK, m1, 4);
            float m8 = __shfl_xor_sync(FULLMASK, m1, 8);
            float mc = __shfl_xor_sync(FULLMASK, m1, 12);
            float mx = fmaxf(fmaxf(m1, m4), fmaxf(m8, mc));
            float p = __expf(z - mx);

#pragma unroll
            for (int it = 0; it < 20; it++) {
                // column sum (over i): lanes differing in bits 2,3
                float c1 = __shfl_xor_sync(FULLMASK, p, 4);
                float c2 = __shfl_xor_sync(FULLMASK, p, 8);
                float c3 = __shfl_xor_sync(FULLMASK, p, 12);
                p = __fdividef(p, ((p + c1) + (c2 + c3)) + 1e-8f);
                // row sum (over j): lanes differing in bits 0,1
                float r1 = __shfl_xor_sync(FULLMASK, p, 1);
                float r2 = __shfl_xor_sync(FULLMASK, p, 2);
                float r3 = __shfl_xor_sync(FULLMASK, p, 3);
                p = __fdividef(p, ((p + r1) + (r2 + r3)) + 1e-8f);
            }

            float hv = 0.f;
            float dd = (dp0[cell] + dp1[cell]) * rs;   // valid for cell < 8
            if (cell < 4) {
                hv = __fdividef(1.0f, 1.0f + __expf(-(a_pre * dd + c_bph)));
            } else if (cell < 8) {
                hv = __fdividef(2.0f, 1.0f + __expf(-(a_post * dd + c_bph)));
            }
            int ii = cell >> 2, jj = cell & 3;
            float hpre_j  = __shfl_sync(FULLMASK, hv, grp + jj);
            float hpost_i = __shfl_sync(FULLMASK, hv, grp + 4 + ii);
            coef[t*16 + cell] = p + hpost_i * hpre_j;
        }
        __syncthreads();

        // ---- Phase D: mixing out[t][i][c] = sum_j M[i][j] * x[t][j][c] ----
        {
            int c4 = tid & 63;     // float4 column chunk (C=256 -> 64 chunks)
            int tg = tid >> 6;     // token group 0..3
            const float4* cf4 = reinterpret_cast<const float4*>(coef);
#pragma unroll
            for (int ttk = 0; ttk < 4; ttk++) {
                int t = tg*4 + ttk;
                float4 m0 = cf4[t*4 + 0];
                float4 m1 = cf4[t*4 + 1];
                float4 m2 = cf4[t*4 + 2];
                float4 m3 = cf4[t*4 + 3];
                const float4* x4 = reinterpret_cast<const float4*>(xb) + t*256;
                float4 xj0 = x4[0*64 + c4];
                float4 xj1 = x4[1*64 + c4];
                float4 xj2 = x4[2*64 + c4];
                float4 xj3 = x4[3*64 + c4];
                float4* o4 = reinterpret_cast<float4*>(out)
                           + ((size_t)tile*TT + t) * 256;
                float4 o;
                o.x = m0.x*xj0.x + m0.y*xj1.x + m0.z*xj2.x + m0.w*xj3.x;
                o.y = m0.x*xj0.y + m0.y*xj1.y + m0.z*xj2.y + m0.w*xj3.y;
                o.z = m0.x*xj0.z + m0.y*xj1.z + m0.z*xj2.z + m0.w*xj3.z;
                o.w = m0.x*xj0.w + m0.y*xj1.w + m0.z*xj2.w + m0.w*xj3.w;
                o4[0*64 + c4] = o;
                o.x = m1.x*xj0.x + m1.y*xj1.x + m1.z*xj2.x + m1.w*xj3.x;
                o.y = m1.x*xj0.y + m1.y*xj1.y + m1.z*xj2.y + m1.w*xj3.y;
                o.z = m1.x*xj0.z + m1.y*xj1.z + m1.z*xj2.z + m1.w*xj3.z;
                o.w = m1.x*xj0.w + m1.y*xj1.w + m1.z*xj2.w + m1.w*xj3.w;
                o4[1*64 + c4] = o;
                o.x = m2.x*xj0.x + m2.y*xj1.x + m2.z*xj2.x + m2.w*xj3.x;
                o.y = m2.x*xj0.y + m2.y*xj1.y + m2.z*xj2.y + m2.w*xj3.y;
                o.z = m2.x*xj0.z + m2.y*xj1.z + m2.z*xj2.z + m2.w*xj3.z;
                o.w = m2.x*xj0.w + m2.y*xj1.w + m2.z*xj2.w + m2.w*xj3.w;
                o4[2*64 + c4] = o;
                o.x = m3.x*xj0.x + m3.y*xj1.x + m3.z*xj2.x + m3.w*xj3.x;
                o.y = m3.x*xj0.y + m3.y*xj1.y + m3.z*xj2.y + m3.w*xj3.y;
                o.z = m3.x*xj0.z + m3.y*xj1.z + m3.z*xj2.z + m3.w*xj3.z;
                o.w = m3.x*xj0.w + m3.y*xj1.w + m3.z*xj2.w + m3.w*xj3.w;
                o4[3*64 + c4] = o;
            }
        }
        __syncthreads();   // xb free for reuse by the prefetch 2 tiles ahead
        buf ^= 1;
    }
}

extern "C" void kernel_launch(void* const* d_in, const int* in_sizes, int n_in,
                              void* d_out, int out_size) {
    const float* x      = (const float*)d_in[0];
    const float* scale  = (const float*)d_in[1];
    const float* w_pre  = (const float*)d_in[2];
    const float* w_post = (const float*)d_in[3];
    const float* w_res  = (const float*)d_in[4];
    const float* apre   = (const float*)d_in[5];
    const float* apost  = (const float*)d_in[6];
    const float* ares   = (const float*)d_in[7];
    const float* b_pre  = (const float*)d_in[8];
    const float* b_post = (const float*)d_in[9];
    const float* b_res  = (const float*)d_in[10];
    float* out = (float*)d_out;

    int BT = in_sizes[0] / NC;        // 32768 tokens
    int nTiles = BT / TT;             // 2048

    size_t smemBytes = (size_t)SMEM_FLOATS * sizeof(float);   // ~133 KB

    int dev = 0;
    cudaGetDevice(&dev);
    int sms = 148;
    cudaDeviceGetAttribute(&sms, cudaDevAttrMultiProcessorCount, dev);
    cudaFuncSetAttribute(fused_streams_kernel,
                         cudaFuncAttributeMaxDynamicSharedMemorySize,
                         (int)smemBytes);

    int grid = sms < nTiles ? sms : nTiles;

    fused_streams_kernel<<<grid, 256, smemBytes>>>(
        x, scale, w_pre, w_post, w_res,
        apre, apost, ares, b_pre, b_post, b_res,
        out, nTiles);
}